// round 5
// baseline (speedup 1.0000x reference)
#include <cuda_runtime.h>

typedef unsigned long long ull;

#define LDR 66          // padded row stride (floats) for column-major act buffers
#define RTILE 64        // rows per CTA
#define NTHREADS 256

// ---------------- device scratch (no runtime allocation allowed) ----------------
__device__ float g_TH[4 * 19 * 64];   // hand layer-1 tables: [card][suit0-4,rank0-13][64]
__device__ float g_TB[5 * 19 * 80];   // board layer-1 tables

// ---------------- output segment descriptors (39 segments of 8 floats) ----------
// kind: 0 = hand_board slice, 1 = embedding lookup, 2 = scalar projection
__device__ const int c_kind[39] = {0,0,0,0,0,0,0,0,
                                   1,1, 1,1,1,1,1, 1,1,1,1,1,
                                   2,2,2,2, 1,1,1, 2, 1,1,1, 1, 1,
                                   2,2,2,2,2,2};
// kind1: emb table id (0 pos,1 action,2 active,3 street,4 nump,5 blind); kind2: state scalar col
__device__ const int c_p0[39]   = {0,0,0,0,0,0,0,0,
                                   3,0, 2,2,2,2,2, 0,0,0,0,0,
                                   40,41,42,43, 0,1,5, 39, 1,0,5, 4, 0,
                                   44,45,46,47,48,49};
// kind1: state index col; kind2: scalar_W row (W_IDX)
__device__ const int c_p1[39]   = {0,0,0,0,0,0,0,0,
                                   18,20, 22,23,24,25,26, 27,28,29,30,31,
                                   0,2,3,5, 35,36,37, 1, 32,33,34, 19, 38,
                                   4,4,4,4,4,4};

__device__ __forceinline__ float leaky(float x) { return x > 0.f ? x : 0.01f * x; }

union F2U { ull u; float2 f; };

// packed dual-fp32 FMA (sm_100+): d = a*b + c elementwise on 2 packed floats
__device__ __forceinline__ ull ffma2(ull a, ull b, ull c) {
    ull d;
    asm("fma.rn.f32x2 %0, %1, %2, %3;" : "=l"(d) : "l"(a), "l"(b), "l"(c));
    return d;
}

// ---------------- prologue: fold embeddings through layer-1 weights -------------
__global__ void build_tables_kernel(const float* __restrict__ suit_emb,
                                    const float* __restrict__ rank_emb,
                                    const float* __restrict__ hW1,
                                    const float* __restrict__ bW1)
{
    int i = blockIdx.x * blockDim.x + threadIdx.x;
    if (i < 4 * 19 * 64) {
        int j = i & 63, e = (i >> 6) % 19, c = i / (64 * 19);
        const float* emb; int dbase;
        if (e < 5) { emb = suit_emb + e * 8;        dbase = 16 * c; }
        else       { emb = rank_emb + (e - 5) * 8;  dbase = 16 * c + 8; }
        float s = 0.f;
        #pragma unroll
        for (int d = 0; d < 8; d++) s += emb[d] * hW1[(dbase + d) * 64 + j];
        g_TH[i] = s;
    } else {
        int ib = i - 4 * 19 * 64;
        if (ib < 5 * 19 * 80) {
            int j = ib % 80, e = (ib / 80) % 19, c = ib / (80 * 19);
            const float* emb; int dbase;
            if (e < 5) { emb = suit_emb + e * 8;       dbase = 16 * c; }
            else       { emb = rank_emb + (e - 5) * 8; dbase = 16 * c + 8; }
            float s = 0.f;
            #pragma unroll
            for (int d = 0; d < 8; d++) s += emb[d] * bW1[(dbase + d) * 80 + j];
            g_TB[ib] = s;
        }
    }
}

// ---------------- register-blocked f32x2 GEMM over a 64-row tile ----------------
// Activations column-major in smem: buf[col*LDR + row]. Each thread owns
// 4 row-pairs (rows 2*ty+16*p, +1) x columns J0 + tx + 32*g (g < NG).
// NTOT is the weight-matrix row stride; the chunk covers cols [J0, J0+NCH).
template<int K1, int K2, int NTOT, int J0, int NCH, bool ACT>
__device__ __forceinline__ void gemm_chunk(const float* __restrict__ in1,
                                           const float* __restrict__ in2,
                                           const float* __restrict__ W,
                                           const float* __restrict__ bias,
                                           float* __restrict__ outb,
                                           int tx, int ty)
{
    constexpr int NG = (NCH + 31) / 32;
    ull acc[4][NG];
    #pragma unroll
    for (int p = 0; p < 4; p++)
        #pragma unroll
        for (int g = 0; g < NG; g++) acc[p][g] = 0ull;

    #pragma unroll 4
    for (int k = 0; k < K1 + K2; k++) {
        const float* src  = (K2 == 0 || k < K1) ? (in1 + k * LDR) : (in2 + (k - K1) * LDR);
        const float* wrow = W + k * NTOT;
        ull wp[NG];
        #pragma unroll
        for (int g = 0; g < NG; g++) {
            int j = J0 + tx + 32 * g;
            float w = (j < J0 + NCH) ? __ldg(wrow + j) : 0.f;
            F2U u; u.f = make_float2(w, w); wp[g] = u.u;
        }
        #pragma unroll
        for (int p = 0; p < 4; p++) {
            ull xp = *(const ull*)(src + 2 * ty + 16 * p);   // broadcast LDS.64
            #pragma unroll
            for (int g = 0; g < NG; g++) acc[p][g] = ffma2(xp, wp[g], acc[p][g]);
        }
    }

    #pragma unroll
    for (int g = 0; g < NG; g++) {
        int j = J0 + tx + 32 * g;
        if (j < J0 + NCH) {
            float bj = __ldg(bias + j);
            #pragma unroll
            for (int p = 0; p < 4; p++) {
                F2U u; u.u = acc[p][g];
                float a0 = u.f.x + bj, a1 = u.f.y + bj;
                if (ACT) { a0 = leaky(a0); a1 = leaky(a1); }
                *(float2*)(outb + j * LDR + 2 * ty + 16 * p) = make_float2(a0, a1);
            }
        }
    }
}

// ---------------- fused main kernel ---------------------------------------------
// Smem (floats): bufH1 4224 | bufH2 4224 | bufB2 5280 | bufB1 5280 = 19008 (74.25 KB)
// bufC (144 cols) aliases [bufH2; bufB2]. 3 CTAs/SM (222.75 KB smem, regs capped 85).
__global__ void __launch_bounds__(NTHREADS, 3)
preprocess_kernel(const float* __restrict__ state,
                  const float* __restrict__ hand_b1, const float* __restrict__ board_b1,
                  const float* __restrict__ hand_W2, const float* __restrict__ hand_b2,
                  const float* __restrict__ hand_W3, const float* __restrict__ hand_b3,
                  const float* __restrict__ board_W2, const float* __restrict__ board_b2,
                  const float* __restrict__ board_W3, const float* __restrict__ board_b3,
                  const float* __restrict__ hb_W1, const float* __restrict__ hb_b1,
                  const float* __restrict__ hb_W2, const float* __restrict__ hb_b2,
                  const float* __restrict__ hb_W3, const float* __restrict__ hb_b3,
                  const float* __restrict__ pos_emb, const float* __restrict__ action_emb,
                  const float* __restrict__ active_emb, const float* __restrict__ street_emb,
                  const float* __restrict__ nump_emb, const float* __restrict__ blind_emb,
                  const float* __restrict__ scalar_W, const float* __restrict__ scalar_b,
                  float* __restrict__ out)
{
    extern __shared__ float smem[];
    float* bufH1  = smem;              // 64*66  = 4224
    float* bufH2  = bufH1 + 4224;      // 64*66  = 4224
    float* bufB2  = bufH2 + 4224;      // 80*66  = 5280
    float* bufB1  = bufB2 + 5280;      // 80*66  = 5280  -> total 19008 floats
    float* bufC   = bufH2;             // 144*66 = 9504, aliases [bufH2; bufB2]

    const int tid = threadIdx.x;
    const int tx = tid & 31, ty = tid >> 5;
    const int row0 = blockIdx.x * RTILE;
    const float* stbase = state + (size_t)row0 * 50;

    // phase 1: hand / board layer-1 via table sums (+bias, leaky). State reads
    // are warp-uniform (whole warp shares a row) -> broadcast LDG, L2-resident.
    for (int i = tid; i < RTILE * 64; i += NTHREADS) {
        int row = i >> 6, j = i & 63;
        const float* st = stbase + row * 50;
        float s = __ldg(hand_b1 + j);
        #pragma unroll
        for (int c = 0; c < 4; c++) {
            int r  = (int)__ldg(st + 2 * c);
            int su = (int)__ldg(st + 2 * c + 1);
            s += __ldg(&g_TH[(c * 19 + su) * 64 + j]) + __ldg(&g_TH[(c * 19 + 5 + r) * 64 + j]);
        }
        bufH1[j * LDR + row] = leaky(s);
    }
    for (int i = tid; i < RTILE * 80; i += NTHREADS) {
        int row = i / 80, j = i % 80;
        const float* st = stbase + row * 50;
        float s = __ldg(board_b1 + j);
        #pragma unroll
        for (int c = 0; c < 5; c++) {
            int r  = (int)__ldg(st + 8 + 2 * c);
            int su = (int)__ldg(st + 9 + 2 * c);
            s += __ldg(&g_TB[(c * 19 + su) * 80 + j]) + __ldg(&g_TB[(c * 19 + 5 + r) * 80 + j]);
        }
        bufB1[j * LDR + row] = leaky(s);
    }
    __syncthreads();

    // hand-L2 and board-L2 are independent: no barrier between them
    gemm_chunk<64, 0, 64, 0, 64, true >(bufH1, nullptr, hand_W2,  hand_b2,  bufH2, tx, ty);
    gemm_chunk<80, 0, 80, 0, 80, true >(bufB1, nullptr, board_W2, board_b2, bufB2, tx, ty);
    __syncthreads();
    // hand-L3 and board-L3 likewise; write back into H1/B1 (now free)
    gemm_chunk<64, 0, 64, 0, 64, false>(bufH2, nullptr, hand_W3,  hand_b3,  bufH1, tx, ty);
    gemm_chunk<80, 0, 80, 0, 80, false>(bufB2, nullptr, board_W3, board_b3, bufB1, tx, ty);
    __syncthreads();
    // hb layer 1 reads concat(hand=bufH1, board=bufB1) -> C (aliases H2+B2, dead).
    // N=144 split into 80+64 column chunks to cap register pressure.
    gemm_chunk<64, 80, 144, 0,  80, true>(bufH1, bufB1, hb_W1, hb_b1, bufC, tx, ty);
    gemm_chunk<64, 80, 144, 80, 64, true>(bufH1, bufB1, hb_W1, hb_b1, bufC, tx, ty);
    __syncthreads();
    gemm_chunk<144, 0, 64, 0, 64, true >(bufC,  nullptr, hb_W2, hb_b2, bufH1, tx, ty);
    __syncthreads();
    // hb-L3: H1 -> cols 0..63 of C region (bufH2 area, free again)
    gemm_chunk<64, 0, 64, 0, 64, false>(bufH1, nullptr, hb_W3, hb_b3, bufH2, tx, ty);
    __syncthreads();
    // final hand_board output lives in bufH2 (cols 0..63)

    // phase 3: assemble 312-float output rows (39 segments of 8)
    const float* embTabs[6] = {pos_emb, action_emb, active_emb, street_emb, nump_emb, blind_emb};
    for (int g = tid; g < RTILE * 39; g += NTHREADS) {
        int row = g / 39, s = g % 39;
        float v[8];
        int kind = c_kind[s];
        if (kind == 0) {
            int cb = s * 8;
            #pragma unroll
            for (int d = 0; d < 8; d++) v[d] = bufH2[(cb + d) * LDR + row];
        } else if (kind == 1) {
            int idx = (int)__ldg(stbase + row * 50 + c_p1[s]);
            const float* e = embTabs[c_p0[s]] + idx * 8;
            #pragma unroll
            for (int d = 0; d < 8; d++) v[d] = __ldg(e + d);
        } else {
            float x = __ldg(stbase + row * 50 + c_p0[s]);
            int wi = c_p1[s];
            #pragma unroll
            for (int d = 0; d < 8; d++)
                v[d] = fmaf(x, __ldg(scalar_W + wi * 8 + d), __ldg(scalar_b + wi * 8 + d));
        }
        float4* o = (float4*)(out + (size_t)(row0 + row) * 312 + s * 8);
        o[0] = make_float4(v[0], v[1], v[2], v[3]);
        o[1] = make_float4(v[4], v[5], v[6], v[7]);
    }
}

// ---------------- launch --------------------------------------------------------
extern "C" void kernel_launch(void* const* d_in, const int* in_sizes, int n_in,
                              void* d_out, int out_size)
{
    const float* state   = (const float*)d_in[0];
    const float* suit    = (const float*)d_in[1];
    const float* rank    = (const float*)d_in[2];
    const float* hW1 = (const float*)d_in[3];  const float* hb1 = (const float*)d_in[4];
    const float* hW2 = (const float*)d_in[5];  const float* hb2 = (const float*)d_in[6];
    const float* hW3 = (const float*)d_in[7];  const float* hb3 = (const float*)d_in[8];
    const float* bW1 = (const float*)d_in[9];  const float* bb1 = (const float*)d_in[10];
    const float* bW2 = (const float*)d_in[11]; const float* bb2 = (const float*)d_in[12];
    const float* bW3 = (const float*)d_in[13]; const float* bb3 = (const float*)d_in[14];
    const float* cW1 = (const float*)d_in[15]; const float* cb1 = (const float*)d_in[16];
    const float* cW2 = (const float*)d_in[17]; const float* cb2 = (const float*)d_in[18];
    const float* cW3 = (const float*)d_in[19]; const float* cb3 = (const float*)d_in[20];
    const float* pos    = (const float*)d_in[21];
    const float* action = (const float*)d_in[22];
    const float* activ  = (const float*)d_in[23];
    const float* street = (const float*)d_in[24];
    const float* nump   = (const float*)d_in[25];
    const float* blind  = (const float*)d_in[26];
    const float* sW     = (const float*)d_in[27];
    const float* sb     = (const float*)d_in[28];
    float* out = (float*)d_out;

    const size_t smemBytes = 19008 * sizeof(float);   // 74.25 KB -> 3 CTAs/SM
    cudaFuncSetAttribute(preprocess_kernel,
                         cudaFuncAttributeMaxDynamicSharedMemorySize, (int)smemBytes);

    build_tables_kernel<<<49, 256>>>(suit, rank, hW1, bW1);

    const int nRows = 512 * 512;
    preprocess_kernel<<<nRows / RTILE, NTHREADS, smemBytes>>>(
        state, hb1, bb1,
        hW2, hb2, hW3, hb3,
        bW2, bb2, bW3, bb3,
        cW1, cb1, cW2, cb2, cW3, cb3,
        pos, action, activ, street, nump, blind,
        sW, sb, out);
}

// round 6
// speedup vs baseline: 1.4646x; 1.4646x over previous
#include <cuda_runtime.h>

typedef unsigned long long ull;

#define LDR 68          // padded row stride (floats), multiple of 4 for float4 I/O
#define RTILE 64        // rows per CTA
#define NTHREADS 256

// ---------------- device scratch (no runtime allocation allowed) ----------------
__device__ float g_TH[4 * 19 * 64];   // hand layer-1 tables: [card][suit0-4,rank0-13][64]
__device__ float g_TB[5 * 19 * 80];   // board layer-1 tables

// ---------------- output segment descriptors (39 segments of 8 floats) ----------
// kind: 0 = hand_board slice, 1 = embedding lookup, 2 = scalar projection
__device__ const int c_kind[39] = {0,0,0,0,0,0,0,0,
                                   1,1, 1,1,1,1,1, 1,1,1,1,1,
                                   2,2,2,2, 1,1,1, 2, 1,1,1, 1, 1,
                                   2,2,2,2,2,2};
// kind1: emb table id (0 pos,1 action,2 active,3 street,4 nump,5 blind); kind2: state scalar col
__device__ const int c_p0[39]   = {0,0,0,0,0,0,0,0,
                                   3,0, 2,2,2,2,2, 0,0,0,0,0,
                                   40,41,42,43, 0,1,5, 39, 1,0,5, 4, 0,
                                   44,45,46,47,48,49};
// kind1: state index col; kind2: scalar_W row (W_IDX)
__device__ const int c_p1[39]   = {0,0,0,0,0,0,0,0,
                                   18,20, 22,23,24,25,26, 27,28,29,30,31,
                                   0,2,3,5, 35,36,37, 1, 32,33,34, 19, 38,
                                   4,4,4,4,4,4};

__device__ __forceinline__ float leaky(float x) { return x > 0.f ? x : 0.01f * x; }

union F2U { ull u; float2 f; };

// packed dual-fp32 FMA (sm_100+): d = a*b + c elementwise on 2 packed floats
__device__ __forceinline__ ull ffma2(ull a, ull b, ull c) {
    ull d;
    asm("fma.rn.f32x2 %0, %1, %2, %3;" : "=l"(d) : "l"(a), "l"(b), "l"(c));
    return d;
}

// ---------------- prologue: fold embeddings through layer-1 weights -------------
__global__ void build_tables_kernel(const float* __restrict__ suit_emb,
                                    const float* __restrict__ rank_emb,
                                    const float* __restrict__ hW1,
                                    const float* __restrict__ bW1)
{
    int i = blockIdx.x * blockDim.x + threadIdx.x;
    if (i < 4 * 19 * 64) {
        int j = i & 63, e = (i >> 6) % 19, c = i / (64 * 19);
        const float* emb; int dbase;
        if (e < 5) { emb = suit_emb + e * 8;        dbase = 16 * c; }
        else       { emb = rank_emb + (e - 5) * 8;  dbase = 16 * c + 8; }
        float s = 0.f;
        #pragma unroll
        for (int d = 0; d < 8; d++) s += emb[d] * hW1[(dbase + d) * 64 + j];
        g_TH[i] = s;
    } else {
        int ib = i - 4 * 19 * 64;
        if (ib < 5 * 19 * 80) {
            int j = ib % 80, e = (ib / 80) % 19, c = ib / (80 * 19);
            const float* emb; int dbase;
            if (e < 5) { emb = suit_emb + e * 8;       dbase = 16 * c; }
            else       { emb = rank_emb + (e - 5) * 8; dbase = 16 * c + 8; }
            float s = 0.f;
            #pragma unroll
            for (int d = 0; d < 8; d++) s += emb[d] * bW1[(dbase + d) * 80 + j];
            g_TB[ib] = s;
        }
    }
}

// ---------------- register-blocked f32x2 GEMM over a 64-row tile ----------------
// Activations column-major in smem: buf[col*LDR + row]. Each thread owns
// 8 CONSECUTIVE rows (8*ty .. 8*ty+7), loaded as two LDS.128 (= 4 packed
// row-pairs), x NG column groups (cols tx + 32*g). Stores are float4.
template<int K1, int K2, int N, bool ACT>
__device__ __forceinline__ void gemm_layer(const float* __restrict__ in1,
                                           const float* __restrict__ in2,
                                           const float* __restrict__ W,
                                           const float* __restrict__ bias,
                                           float* __restrict__ outb,
                                           int tx, int ty)
{
    constexpr int NG = (N + 31) / 32;
    ull acc[4][NG];
    #pragma unroll
    for (int p = 0; p < 4; p++)
        #pragma unroll
        for (int g = 0; g < NG; g++) acc[p][g] = 0ull;

    const int r0 = 8 * ty;

    #pragma unroll 4
    for (int k = 0; k < K1 + K2; k++) {
        const float* src  = (K2 == 0 || k < K1) ? (in1 + k * LDR) : (in2 + (k - K1) * LDR);
        const float* wrow = W + k * N;
        ull wp[NG];
        #pragma unroll
        for (int g = 0; g < NG; g++) {
            int j = tx + 32 * g;
            float w = (j < N) ? __ldg(wrow + j) : 0.f;
            F2U u; u.f = make_float2(w, w); wp[g] = u.u;
        }
        // two 128-bit broadcast loads cover rows r0..r0+7 as 4 packed pairs
        ulonglong2 xa = *(const ulonglong2*)(src + r0);
        ulonglong2 xb = *(const ulonglong2*)(src + r0 + 4);
        ull xp[4] = {xa.x, xa.y, xb.x, xb.y};
        #pragma unroll
        for (int p = 0; p < 4; p++)
            #pragma unroll
            for (int g = 0; g < NG; g++) acc[p][g] = ffma2(xp[p], wp[g], acc[p][g]);
    }

    #pragma unroll
    for (int g = 0; g < NG; g++) {
        int j = tx + 32 * g;
        if (j < N) {
            float bj = __ldg(bias + j);
            float r[8];
            #pragma unroll
            for (int p = 0; p < 4; p++) {
                F2U u; u.u = acc[p][g];
                float a0 = u.f.x + bj, a1 = u.f.y + bj;
                if (ACT) { a0 = leaky(a0); a1 = leaky(a1); }
                r[2 * p] = a0; r[2 * p + 1] = a1;
            }
            float* o = outb + j * LDR + r0;
            *(float4*)(o)     = make_float4(r[0], r[1], r[2], r[3]);
            *(float4*)(o + 4) = make_float4(r[4], r[5], r[6], r[7]);
        }
    }
}

// ---------------- fused main kernel ---------------------------------------------
// Smem (floats): sstate 3200 | bufH1 4352 | bufH2 4352 | bufB2 5440 | bufB1 5440
//   total 22784 (~89 KB) -> 2 CTAs/SM. bufC (144 cols) aliases [bufH2; bufB2].
__global__ void __launch_bounds__(NTHREADS, 2)
preprocess_kernel(const float* __restrict__ state,
                  const float* __restrict__ hand_b1, const float* __restrict__ board_b1,
                  const float* __restrict__ hand_W2, const float* __restrict__ hand_b2,
                  const float* __restrict__ hand_W3, const float* __restrict__ hand_b3,
                  const float* __restrict__ board_W2, const float* __restrict__ board_b2,
                  const float* __restrict__ board_W3, const float* __restrict__ board_b3,
                  const float* __restrict__ hb_W1, const float* __restrict__ hb_b1,
                  const float* __restrict__ hb_W2, const float* __restrict__ hb_b2,
                  const float* __restrict__ hb_W3, const float* __restrict__ hb_b3,
                  const float* __restrict__ pos_emb, const float* __restrict__ action_emb,
                  const float* __restrict__ active_emb, const float* __restrict__ street_emb,
                  const float* __restrict__ nump_emb, const float* __restrict__ blind_emb,
                  const float* __restrict__ scalar_W, const float* __restrict__ scalar_b,
                  float* __restrict__ out)
{
    extern __shared__ float smem[];
    float* sstate = smem;              // 64*50  = 3200
    float* bufH1  = sstate + 3200;     // 64*68  = 4352
    float* bufH2  = bufH1 + 4352;      // 64*68  = 4352
    float* bufB2  = bufH2 + 4352;      // 80*68  = 5440
    float* bufB1  = bufB2 + 5440;      // 80*68  = 5440  -> total 22784 floats
    float* bufC   = bufH2;             // 144*68 = 9792, aliases [bufH2; bufB2]

    const int tid = threadIdx.x;
    const int tx = tid & 31, ty = tid >> 5;
    const int row0 = blockIdx.x * RTILE;

    // stage state tile
    for (int i = tid; i < RTILE * 50; i += NTHREADS) sstate[i] = state[(size_t)row0 * 50 + i];
    __syncthreads();

    // phase 1: hand / board layer-1 via table sums (+bias, leaky)
    for (int i = tid; i < RTILE * 64; i += NTHREADS) {
        int row = i >> 6, j = i & 63;
        const float* st = sstate + row * 50;
        float s = __ldg(hand_b1 + j);
        #pragma unroll
        for (int c = 0; c < 4; c++) {
            int r  = (int)st[2 * c];
            int su = (int)st[2 * c + 1];
            s += __ldg(&g_TH[(c * 19 + su) * 64 + j]) + __ldg(&g_TH[(c * 19 + 5 + r) * 64 + j]);
        }
        bufH1[j * LDR + row] = leaky(s);
    }
    for (int i = tid; i < RTILE * 80; i += NTHREADS) {
        int row = i / 80, j = i % 80;
        const float* st = sstate + row * 50;
        float s = __ldg(board_b1 + j);
        #pragma unroll
        for (int c = 0; c < 5; c++) {
            int r  = (int)st[8 + 2 * c];
            int su = (int)st[9 + 2 * c];
            s += __ldg(&g_TB[(c * 19 + su) * 80 + j]) + __ldg(&g_TB[(c * 19 + 5 + r) * 80 + j]);
        }
        bufB1[j * LDR + row] = leaky(s);
    }
    __syncthreads();

    // hand-L2 and board-L2 are independent: no barrier between them
    gemm_layer<64, 0, 64, true >(bufH1, nullptr, hand_W2,  hand_b2,  bufH2, tx, ty);
    gemm_layer<80, 0, 80, true >(bufB1, nullptr, board_W2, board_b2, bufB2, tx, ty);
    __syncthreads();
    // hand-L3 and board-L3 likewise; write back into H1/B1 (now free)
    gemm_layer<64, 0, 64, false>(bufH2, nullptr, hand_W3,  hand_b3,  bufH1, tx, ty);
    gemm_layer<80, 0, 80, false>(bufB2, nullptr, board_W3, board_b3, bufB1, tx, ty);
    __syncthreads();
    // hb layer 1 reads concat(hand=bufH1, board=bufB1) -> C (aliases H2+B2, dead)
    gemm_layer<64, 80, 144, true>(bufH1, bufB1, hb_W1, hb_b1, bufC, tx, ty);
    __syncthreads();
    gemm_layer<144, 0, 64, true >(bufC,  nullptr, hb_W2, hb_b2, bufH1, tx, ty);
    __syncthreads();
    // hb-L3: H1 -> bufH2 area (free again)
    gemm_layer<64, 0, 64, false>(bufH1, nullptr, hb_W3, hb_b3, bufH2, tx, ty);
    __syncthreads();
    // final hand_board output lives in bufH2 (cols 0..63)

    // phase 3: assemble 312-float output rows (39 segments of 8)
    const float* embTabs[6] = {pos_emb, action_emb, active_emb, street_emb, nump_emb, blind_emb};
    for (int g = tid; g < RTILE * 39; g += NTHREADS) {
        int row = g / 39, s = g % 39;
        float v[8];
        int kind = c_kind[s];
        if (kind == 0) {
            int cb = s * 8;
            #pragma unroll
            for (int d = 0; d < 8; d++) v[d] = bufH2[(cb + d) * LDR + row];
        } else if (kind == 1) {
            int idx = (int)sstate[row * 50 + c_p1[s]];
            const float* e = embTabs[c_p0[s]] + idx * 8;
            #pragma unroll
            for (int d = 0; d < 8; d++) v[d] = __ldg(e + d);
        } else {
            float x = sstate[row * 50 + c_p0[s]];
            int wi = c_p1[s];
            #pragma unroll
            for (int d = 0; d < 8; d++)
                v[d] = fmaf(x, __ldg(scalar_W + wi * 8 + d), __ldg(scalar_b + wi * 8 + d));
        }
        float4* o = (float4*)(out + (size_t)(row0 + row) * 312 + s * 8);
        o[0] = make_float4(v[0], v[1], v[2], v[3]);
        o[1] = make_float4(v[4], v[5], v[6], v[7]);
    }
}

// ---------------- launch --------------------------------------------------------
extern "C" void kernel_launch(void* const* d_in, const int* in_sizes, int n_in,
                              void* d_out, int out_size)
{
    const float* state   = (const float*)d_in[0];
    const float* suit    = (const float*)d_in[1];
    const float* rank    = (const float*)d_in[2];
    const float* hW1 = (const float*)d_in[3];  const float* hb1 = (const float*)d_in[4];
    const float* hW2 = (const float*)d_in[5];  const float* hb2 = (const float*)d_in[6];
    const float* hW3 = (const float*)d_in[7];  const float* hb3 = (const float*)d_in[8];
    const float* bW1 = (const float*)d_in[9];  const float* bb1 = (const float*)d_in[10];
    const float* bW2 = (const float*)d_in[11]; const float* bb2 = (const float*)d_in[12];
    const float* bW3 = (const float*)d_in[13]; const float* bb3 = (const float*)d_in[14];
    const float* cW1 = (const float*)d_in[15]; const float* cb1 = (const float*)d_in[16];
    const float* cW2 = (const float*)d_in[17]; const float* cb2 = (const float*)d_in[18];
    const float* cW3 = (const float*)d_in[19]; const float* cb3 = (const float*)d_in[20];
    const float* pos    = (const float*)d_in[21];
    const float* action = (const float*)d_in[22];
    const float* activ  = (const float*)d_in[23];
    const float* street = (const float*)d_in[24];
    const float* nump   = (const float*)d_in[25];
    const float* blind  = (const float*)d_in[26];
    const float* sW     = (const float*)d_in[27];
    const float* sb     = (const float*)d_in[28];
    float* out = (float*)d_out;

    const size_t smemBytes = 22784 * sizeof(float);   // ~89 KB -> 2 CTAs/SM
    cudaFuncSetAttribute(preprocess_kernel,
                         cudaFuncAttributeMaxDynamicSharedMemorySize, (int)smemBytes);

    build_tables_kernel<<<49, 256>>>(suit, rank, hW1, bW1);

    const int nRows = 512 * 512;
    preprocess_kernel<<<nRows / RTILE, NTHREADS, smemBytes>>>(
        state, hb1, bb1,
        hW2, hb2, hW3, hb3,
        bW2, bb2, bW3, bb3,
        cW1, cb1, cW2, cb2, cW3, cb3,
        pos, action, activ, street, nump, blind,
        sW, sb, out);
}

// round 7
// speedup vs baseline: 1.6299x; 1.1129x over previous
#include <cuda_runtime.h>

typedef unsigned long long ull;

#define LDR 68          // padded row stride (floats), multiple of 4 for float4 I/O
#define RTILE 64        // rows per CTA
#define NTHREADS 256

// ---------------- device scratch (no runtime allocation allowed) ----------------
__device__ float g_TH[4 * 19 * 64];   // hand layer-1 tables: [card][suit0-4,rank0-13][64]
__device__ float g_TB[5 * 19 * 80];   // board layer-1 tables
__device__ float g_W[55040];          // packed weights, layout [K/4][N][4]

// packed-weight offsets (floats)
#define OFF_HW2 0
#define OFF_HW3 4096
#define OFF_BW2 8192
#define OFF_BW3 14592
#define OFF_CW1 20992
#define OFF_CW2 41728
#define OFF_CW3 50944

// ---------------- output segment descriptors (39 segments of 8 floats) ----------
// kind: 0 = hand_board slice, 1 = embedding lookup, 2 = scalar projection
__device__ const int c_kind[39] = {0,0,0,0,0,0,0,0,
                                   1,1, 1,1,1,1,1, 1,1,1,1,1,
                                   2,2,2,2, 1,1,1, 2, 1,1,1, 1, 1,
                                   2,2,2,2,2,2};
// kind1: emb table id (0 pos,1 action,2 active,3 street,4 nump,5 blind); kind2: state scalar col
__device__ const int c_p0[39]   = {0,0,0,0,0,0,0,0,
                                   3,0, 2,2,2,2,2, 0,0,0,0,0,
                                   40,41,42,43, 0,1,5, 39, 1,0,5, 4, 0,
                                   44,45,46,47,48,49};
// kind1: state index col; kind2: scalar_W row (W_IDX)
__device__ const int c_p1[39]   = {0,0,0,0,0,0,0,0,
                                   18,20, 22,23,24,25,26, 27,28,29,30,31,
                                   0,2,3,5, 35,36,37, 1, 32,33,34, 19, 38,
                                   4,4,4,4,4,4};

__device__ __forceinline__ float leaky(float x) { return x > 0.f ? x : 0.01f * x; }

union F2U { ull u; float2 f; };

// packed dual-fp32 FMA (sm_100+): d = a*b + c elementwise on 2 packed floats
__device__ __forceinline__ ull ffma2(ull a, ull b, ull c) {
    ull d;
    asm("fma.rn.f32x2 %0, %1, %2, %3;" : "=l"(d) : "l"(a), "l"(b), "l"(c));
    return d;
}

// ---------------- prologue 1: fold embeddings through layer-1 weights -----------
__global__ void build_tables_kernel(const float* __restrict__ suit_emb,
                                    const float* __restrict__ rank_emb,
                                    const float* __restrict__ hW1,
                                    const float* __restrict__ bW1)
{
    int i = blockIdx.x * blockDim.x + threadIdx.x;
    if (i < 4 * 19 * 64) {
        int j = i & 63, e = (i >> 6) % 19, c = i / (64 * 19);
        const float* emb; int dbase;
        if (e < 5) { emb = suit_emb + e * 8;        dbase = 16 * c; }
        else       { emb = rank_emb + (e - 5) * 8;  dbase = 16 * c + 8; }
        float s = 0.f;
        #pragma unroll
        for (int d = 0; d < 8; d++) s += emb[d] * hW1[(dbase + d) * 64 + j];
        g_TH[i] = s;
    } else {
        int ib = i - 4 * 19 * 64;
        if (ib < 5 * 19 * 80) {
            int j = ib % 80, e = (ib / 80) % 19, c = ib / (80 * 19);
            const float* emb; int dbase;
            if (e < 5) { emb = suit_emb + e * 8;       dbase = 16 * c; }
            else       { emb = rank_emb + (e - 5) * 8; dbase = 16 * c + 8; }
            float s = 0.f;
            #pragma unroll
            for (int d = 0; d < 8; d++) s += emb[d] * bW1[(dbase + d) * 80 + j];
            g_TB[ib] = s;
        }
    }
}

// ---------------- prologue 2: repack a weight matrix [K][N] -> [K/4][N][4] ------
__global__ void pack_weights_kernel(const float* __restrict__ src,
                                    int K, int N, int dstOff)
{
    int i = blockIdx.x * blockDim.x + threadIdx.x;
    if (i < K * N) {
        int k = i / N, j = i - k * N;
        g_W[dstOff + ((k >> 2) * N + j) * 4 + (k & 3)] = src[i];
    }
}

// ---------------- GEMM building blocks ------------------------------------------
// Activations column-major in smem: buf[col*LDR + row]. Each thread owns
// 8 consecutive rows (8*ty..8*ty+7) as 4 packed pairs x NG column groups.
// Weights come from g_W packed [K/4][N][4]: one float4 per group per 4 k's.
template<int K, int N, int NG>
__device__ __forceinline__ void gemm_accum(const float* __restrict__ in,
                                           const float* __restrict__ Wp,
                                           ull (&acc)[4][NG],
                                           int tx, int r0)
{
    #pragma unroll 2
    for (int k4 = 0; k4 < K / 4; k4++) {
        float4 wv[NG];
        #pragma unroll
        for (int g = 0; g < NG; g++) {
            int j = tx + 32 * g;
            wv[g] = (j < N) ? __ldg((const float4*)(Wp + ((size_t)k4 * N + j) * 4))
                            : make_float4(0.f, 0.f, 0.f, 0.f);
        }
        #pragma unroll
        for (int r = 0; r < 4; r++) {
            const float* src = in + (k4 * 4 + r) * LDR;
            ulonglong2 xa = *(const ulonglong2*)(src + r0);
            ulonglong2 xb = *(const ulonglong2*)(src + r0 + 4);
            ull xp[4] = {xa.x, xa.y, xb.x, xb.y};
            #pragma unroll
            for (int g = 0; g < NG; g++) {
                float w = (r == 0) ? wv[g].x : (r == 1) ? wv[g].y
                        : (r == 2) ? wv[g].z : wv[g].w;
                F2U u; u.f = make_float2(w, w);
                #pragma unroll
                for (int p = 0; p < 4; p++) acc[p][g] = ffma2(xp[p], u.u, acc[p][g]);
            }
        }
    }
}

template<int N, int NG, bool ACT>
__device__ __forceinline__ void gemm_epilogue(ull (&acc)[4][NG],
                                              const float* __restrict__ bias,
                                              float* __restrict__ outb,
                                              int tx, int r0)
{
    #pragma unroll
    for (int g = 0; g < NG; g++) {
        int j = tx + 32 * g;
        if (j < N) {
            float bj = __ldg(bias + j);
            float r[8];
            #pragma unroll
            for (int p = 0; p < 4; p++) {
                F2U u; u.u = acc[p][g];
                float a0 = u.f.x + bj, a1 = u.f.y + bj;
                if (ACT) { a0 = leaky(a0); a1 = leaky(a1); }
                r[2 * p] = a0; r[2 * p + 1] = a1;
            }
            float* o = outb + j * LDR + r0;
            *(float4*)(o)     = make_float4(r[0], r[1], r[2], r[3]);
            *(float4*)(o + 4) = make_float4(r[4], r[5], r[6], r[7]);
        }
    }
}

template<int K1, int K2, int N, bool ACT>
__device__ __forceinline__ void gemm_layer(const float* __restrict__ in1,
                                           const float* __restrict__ in2,
                                           const float* __restrict__ Wp,
                                           const float* __restrict__ bias,
                                           float* __restrict__ outb,
                                           int tx, int ty)
{
    constexpr int NG = (N + 31) / 32;
    const int r0 = 8 * ty;
    ull acc[4][NG];
    #pragma unroll
    for (int p = 0; p < 4; p++)
        #pragma unroll
        for (int g = 0; g < NG; g++) acc[p][g] = 0ull;

    gemm_accum<K1, N, NG>(in1, Wp, acc, tx, r0);
    if (K2 > 0)
        gemm_accum<K2, N, NG>(in2, Wp + (size_t)(K1 / 4) * N * 4, acc, tx, r0);

    gemm_epilogue<N, NG, ACT>(acc, bias, outb, tx, r0);
}

// ---------------- fused main kernel ---------------------------------------------
// Smem (floats): sstate 3200 | bufH1 4352 | bufH2 4352 | bufB2 5440 | bufB1 5440
//   total 22784 (~89 KB) -> 2 CTAs/SM. bufC (144 cols) aliases [bufH2; bufB2].
__global__ void __launch_bounds__(NTHREADS, 2)
preprocess_kernel(const float* __restrict__ state,
                  const float* __restrict__ hand_b1, const float* __restrict__ board_b1,
                  const float* __restrict__ hand_b2, const float* __restrict__ hand_b3,
                  const float* __restrict__ board_b2, const float* __restrict__ board_b3,
                  const float* __restrict__ hb_b1, const float* __restrict__ hb_b2,
                  const float* __restrict__ hb_b3,
                  const float* __restrict__ pos_emb, const float* __restrict__ action_emb,
                  const float* __restrict__ active_emb, const float* __restrict__ street_emb,
                  const float* __restrict__ nump_emb, const float* __restrict__ blind_emb,
                  const float* __restrict__ scalar_W, const float* __restrict__ scalar_b,
                  float* __restrict__ out)
{
    extern __shared__ float smem[];
    float* sstate = smem;              // 64*50  = 3200
    float* bufH1  = sstate + 3200;     // 64*68  = 4352
    float* bufH2  = bufH1 + 4352;      // 64*68  = 4352
    float* bufB2  = bufH2 + 4352;      // 80*68  = 5440
    float* bufB1  = bufB2 + 5440;      // 80*68  = 5440  -> total 22784 floats
    float* bufC   = bufH2;             // 144*68 = 9792, aliases [bufH2; bufB2]

    const int tid = threadIdx.x;
    const int tx = tid & 31, ty = tid >> 5;
    const int row0 = blockIdx.x * RTILE;

    // stage state tile
    for (int i = tid; i < RTILE * 50; i += NTHREADS) sstate[i] = state[(size_t)row0 * 50 + i];
    __syncthreads();

    // phase 1: hand / board layer-1 via table sums (+bias, leaky)
    for (int i = tid; i < RTILE * 64; i += NTHREADS) {
        int row = i >> 6, j = i & 63;
        const float* st = sstate + row * 50;
        float s = __ldg(hand_b1 + j);
        #pragma unroll
        for (int c = 0; c < 4; c++) {
            int r  = (int)st[2 * c];
            int su = (int)st[2 * c + 1];
            s += __ldg(&g_TH[(c * 19 + su) * 64 + j]) + __ldg(&g_TH[(c * 19 + 5 + r) * 64 + j]);
        }
        bufH1[j * LDR + row] = leaky(s);
    }
    for (int i = tid; i < RTILE * 80; i += NTHREADS) {
        int row = i / 80, j = i % 80;
        const float* st = sstate + row * 50;
        float s = __ldg(board_b1 + j);
        #pragma unroll
        for (int c = 0; c < 5; c++) {
            int r  = (int)st[8 + 2 * c];
            int su = (int)st[9 + 2 * c];
            s += __ldg(&g_TB[(c * 19 + su) * 80 + j]) + __ldg(&g_TB[(c * 19 + 5 + r) * 80 + j]);
        }
        bufB1[j * LDR + row] = leaky(s);
    }
    __syncthreads();

    // hand-L2 and board-L2 are independent: no barrier between them
    gemm_layer<64, 0, 64, true >(bufH1, nullptr, g_W + OFF_HW2, hand_b2,  bufH2, tx, ty);
    gemm_layer<80, 0, 80, true >(bufB1, nullptr, g_W + OFF_BW2, board_b2, bufB2, tx, ty);
    __syncthreads();
    // hand-L3 and board-L3 likewise; write back into H1/B1 (now free)
    gemm_layer<64, 0, 64, false>(bufH2, nullptr, g_W + OFF_HW3, hand_b3,  bufH1, tx, ty);
    gemm_layer<80, 0, 80, false>(bufB2, nullptr, g_W + OFF_BW3, board_b3, bufB1, tx, ty);
    __syncthreads();
    // hb layer 1 reads concat(hand=bufH1, board=bufB1) -> C (aliases H2+B2, dead)
    gemm_layer<64, 80, 144, true>(bufH1, bufB1, g_W + OFF_CW1, hb_b1, bufC, tx, ty);
    __syncthreads();
    gemm_layer<144, 0, 64, true >(bufC,  nullptr, g_W + OFF_CW2, hb_b2, bufH1, tx, ty);
    __syncthreads();
    // hb-L3: H1 -> bufH2 area (free again)
    gemm_layer<64, 0, 64, false>(bufH1, nullptr, g_W + OFF_CW3, hb_b3, bufH2, tx, ty);
    __syncthreads();
    // final hand_board output lives in bufH2 (cols 0..63)

    // phase 3: assemble 312-float output rows (39 segments of 8)
    const float* embTabs[6] = {pos_emb, action_emb, active_emb, street_emb, nump_emb, blind_emb};
    for (int g = tid; g < RTILE * 39; g += NTHREADS) {
        int row = g / 39, s = g % 39;
        float v[8];
        int kind = c_kind[s];
        if (kind == 0) {
            int cb = s * 8;
            #pragma unroll
            for (int d = 0; d < 8; d++) v[d] = bufH2[(cb + d) * LDR + row];
        } else if (kind == 1) {
            int idx = (int)sstate[row * 50 + c_p1[s]];
            const float* e = embTabs[c_p0[s]] + idx * 8;
            #pragma unroll
            for (int d = 0; d < 8; d++) v[d] = __ldg(e + d);
        } else {
            float x = sstate[row * 50 + c_p0[s]];
            int wi = c_p1[s];
            #pragma unroll
            for (int d = 0; d < 8; d++)
                v[d] = fmaf(x, __ldg(scalar_W + wi * 8 + d), __ldg(scalar_b + wi * 8 + d));
        }
        float4* o = (float4*)(out + (size_t)(row0 + row) * 312 + s * 8);
        o[0] = make_float4(v[0], v[1], v[2], v[3]);
        o[1] = make_float4(v[4], v[5], v[6], v[7]);
    }
}

// ---------------- launch --------------------------------------------------------
extern "C" void kernel_launch(void* const* d_in, const int* in_sizes, int n_in,
                              void* d_out, int out_size)
{
    const float* state   = (const float*)d_in[0];
    const float* suit    = (const float*)d_in[1];
    const float* rank    = (const float*)d_in[2];
    const float* hW1 = (const float*)d_in[3];  const float* hb1 = (const float*)d_in[4];
    const float* hW2 = (const float*)d_in[5];  const float* hb2 = (const float*)d_in[6];
    const float* hW3 = (const float*)d_in[7];  const float* hb3 = (const float*)d_in[8];
    const float* bW1 = (const float*)d_in[9];  const float* bb1 = (const float*)d_in[10];
    const float* bW2 = (const float*)d_in[11]; const float* bb2 = (const float*)d_in[12];
    const float* bW3 = (const float*)d_in[13]; const float* bb3 = (const float*)d_in[14];
    const float* cW1 = (const float*)d_in[15]; const float* cb1 = (const float*)d_in[16];
    const float* cW2 = (const float*)d_in[17]; const float* cb2 = (const float*)d_in[18];
    const float* cW3 = (const float*)d_in[19]; const float* cb3 = (const float*)d_in[20];
    const float* pos    = (const float*)d_in[21];
    const float* action = (const float*)d_in[22];
    const float* activ  = (const float*)d_in[23];
    const float* street = (const float*)d_in[24];
    const float* nump   = (const float*)d_in[25];
    const float* blind  = (const float*)d_in[26];
    const float* sW     = (const float*)d_in[27];
    const float* sb     = (const float*)d_in[28];
    float* out = (float*)d_out;

    const size_t smemBytes = 22784 * sizeof(float);   // ~89 KB -> 2 CTAs/SM
    cudaFuncSetAttribute(preprocess_kernel,
                         cudaFuncAttributeMaxDynamicSharedMemorySize, (int)smemBytes);

    build_tables_kernel<<<49, 256>>>(suit, rank, hW1, bW1);
    pack_weights_kernel<<<(64*64  + 255)/256, 256>>>(hW2, 64, 64,  OFF_HW2);
    pack_weights_kernel<<<(64*64  + 255)/256, 256>>>(hW3, 64, 64,  OFF_HW3);
    pack_weights_kernel<<<(80*80  + 255)/256, 256>>>(bW2, 80, 80,  OFF_BW2);
    pack_weights_kernel<<<(80*80  + 255)/256, 256>>>(bW3, 80, 80,  OFF_BW3);
    pack_weights_kernel<<<(144*144+ 255)/256, 256>>>(cW1, 144, 144, OFF_CW1);
    pack_weights_kernel<<<(144*64 + 255)/256, 256>>>(cW2, 144, 64,  OFF_CW2);
    pack_weights_kernel<<<(64*64  + 255)/256, 256>>>(cW3, 64, 64,  OFF_CW3);

    const int nRows = 512 * 512;
    preprocess_kernel<<<nRows / RTILE, NTHREADS, smemBytes>>>(
        state, hb1, bb1,
        hb2, hb3, bb2, bb3,
        cb1, cb2, cb3,
        pos, action, activ, street, nump, blind,
        sW, sb, out);
}